// round 1
// baseline (speedup 1.0000x reference)
#include <cuda_runtime.h>

#define B_  4
#define S_  2048
#define D_  1024
#define H_  16
#define DK_ 64
#define M_  (B_ * S_)          // 8192
#define QKV_ELEMS (B_ * H_ * S_ * DK_)   // 8388608

// Scratch (allowed: __device__ globals, no runtime allocation)
__device__ float g_Q[QKV_ELEMS];
__device__ float g_K[QKV_ELEMS];
__device__ float g_V[QKV_ELEMS];
__device__ float g_O[QKV_ELEMS];

// ---------------------------------------------------------------------------
// Kernel 1: QKV projection.
//   C[m][j] = sum_d x[m][d] * W[h][d][k] + bias[h][k],  j = h*64 + k
//   Output layout: [B, H, S, DK]  -> ((b*H + h)*S + s)*DK + k
// 128x128x16 tiling, 256 threads, 8x8 per-thread micro-tile. blockIdx.z picks Q/K/V.
// ---------------------------------------------------------------------------
__global__ __launch_bounds__(256) void qkv_gemm(
    const float* __restrict__ x,
    const float* __restrict__ Wq, const float* __restrict__ bq,
    const float* __restrict__ Wk, const float* __restrict__ bk,
    const float* __restrict__ Wv, const float* __restrict__ bv)
{
    const float* W; const float* bias; float* out;
    if (blockIdx.z == 0)      { W = Wq; bias = bq; out = g_Q; }
    else if (blockIdx.z == 1) { W = Wk; bias = bk; out = g_K; }
    else                      { W = Wv; bias = bv; out = g_V; }

    __shared__ float As[16][128];   // [k][m] (transposed)
    __shared__ float Bs[16][128];   // [k][n]

    const int tid  = threadIdx.x;
    const int ty   = tid >> 4;          // 0..15
    const int tx   = tid & 15;          // 0..15
    const int m0   = blockIdx.x * 128;
    const int n0   = blockIdx.y * 128;

    // A-tile load mapping: 128 rows x 16 cols, 2 float4 per thread
    const int arow = tid >> 2;          // 0..63 (and +64)
    const int acol = (tid & 3) << 2;    // 0,4,8,12
    // B-tile load mapping: 16 rows x 128 cols, 2 float4 per thread
    const int brow = tid >> 5;          // 0..7 (and +8)
    const int bcol = (tid & 31) << 2;   // 0..124

    // weight column base for this thread's B loads
    const int jb   = n0 + bcol;
    const float* wp = W + (jb >> 6) * (D_ * DK_) + (jb & 63);

    float acc[8][8];
#pragma unroll
    for (int i = 0; i < 8; i++)
#pragma unroll
        for (int j = 0; j < 8; j++) acc[i][j] = 0.0f;

    for (int k0 = 0; k0 < D_; k0 += 16) {
        float4 a0 = *(const float4*)&x[(size_t)(m0 + arow)      * D_ + k0 + acol];
        float4 a1 = *(const float4*)&x[(size_t)(m0 + arow + 64) * D_ + k0 + acol];
        float4 b0 = *(const float4*)&wp[(size_t)(k0 + brow)     * DK_];
        float4 b1 = *(const float4*)&wp[(size_t)(k0 + brow + 8) * DK_];

        __syncthreads();
        As[acol + 0][arow] = a0.x; As[acol + 1][arow] = a0.y;
        As[acol + 2][arow] = a0.z; As[acol + 3][arow] = a0.w;
        As[acol + 0][arow + 64] = a1.x; As[acol + 1][arow + 64] = a1.y;
        As[acol + 2][arow + 64] = a1.z; As[acol + 3][arow + 64] = a1.w;
        *(float4*)&Bs[brow][bcol]     = b0;
        *(float4*)&Bs[brow + 8][bcol] = b1;
        __syncthreads();

#pragma unroll
        for (int kk = 0; kk < 16; kk++) {
            float4 av0 = *(const float4*)&As[kk][ty * 8];
            float4 av1 = *(const float4*)&As[kk][ty * 8 + 4];
            float4 bv0 = *(const float4*)&Bs[kk][tx * 8];
            float4 bv1 = *(const float4*)&Bs[kk][tx * 8 + 4];
            float ar[8] = {av0.x, av0.y, av0.z, av0.w, av1.x, av1.y, av1.z, av1.w};
            float br[8] = {bv0.x, bv0.y, bv0.z, bv0.w, bv1.x, bv1.y, bv1.z, bv1.w};
#pragma unroll
            for (int i = 0; i < 8; i++)
#pragma unroll
                for (int j = 0; j < 8; j++)
                    acc[i][j] += ar[i] * br[j];
        }
    }

    // Epilogue: scatter into [B,H,S,DK] with bias
    const int bb   = m0 >> 11;                 // batch (128 | 2048 -> uniform per block)
    const int jcol = n0 + tx * 8;              // 8 cols stay inside one head (8 | 64)
    const int h    = jcol >> 6;
    const int kin  = jcol & 63;
    float bz[8];
#pragma unroll
    for (int j = 0; j < 8; j++) bz[j] = bias[jcol + j];

#pragma unroll
    for (int i = 0; i < 8; i++) {
        const int s = (m0 & 2047) + ty * 8 + i;
        float* orow = out + (size_t)((bb * H_ + h) * S_ + s) * DK_ + kin;
        float4 o0 = make_float4(acc[i][0] + bz[0], acc[i][1] + bz[1],
                                acc[i][2] + bz[2], acc[i][3] + bz[3]);
        float4 o1 = make_float4(acc[i][4] + bz[4], acc[i][5] + bz[5],
                                acc[i][6] + bz[6], acc[i][7] + bz[7]);
        *(float4*)&orow[0] = o0;
        *(float4*)&orow[4] = o1;
    }
}

// ---------------------------------------------------------------------------
// Kernel 2: causal flash attention, fp32.
//   Per (b,h): Q,K,V are [S, DK] contiguous. 64-query x 64-key tiles,
//   online softmax, O accumulated in registers, causal tile skipping.
//   Smem: Qs[r][k] 16KB, KPs 16KB (K k-major, reused for P), Vs 16KB = 48KB.
// ---------------------------------------------------------------------------
__global__ __launch_bounds__(256) void attn_kernel()
{
    const int qt = blockIdx.x;   // query tile 0..31
    const int bh = blockIdx.y;   // 0..63
    const float* Qp = g_Q + (size_t)bh * S_ * DK_;
    const float* Kp = g_K + (size_t)bh * S_ * DK_;
    const float* Vp = g_V + (size_t)bh * S_ * DK_;
    float*       Op = g_O + (size_t)bh * S_ * DK_;

    __shared__ float Qs[64][64];    // [r][k], Q pre-scaled by 1/8
    __shared__ float KPs[64][64];   // phase 1: K as [k][c]; phase 2: P as [r][c]
    __shared__ float Vs[64][64];    // [c][d]

    const int tid = threadIdx.x;
    const int ty  = tid >> 4;       // 0..15 -> rows ty*4..ty*4+3
    const int tx  = tid & 15;       // 0..15 -> cols tx*4..tx*4+3
    const unsigned FULL = 0xffffffffu;

    // tile-copy mapping (row-major float4)
    const int lr = tid >> 4;            // 0..15 (+16,+32,+48)
    const int lc = (tid & 15) << 2;     // 0..60
    // K transposed-store mapping: conflict-free STS (distinct banks via c)
    const int kc = tid & 63;            // kv column 0..63
    const int kq = tid >> 6;            // 0..3

    const int q0 = qt * 64;

    // Load Q once (scaled by softmax scale 1/sqrt(64) = 0.125)
#pragma unroll
    for (int rr = 0; rr < 64; rr += 16) {
        float4 q = *(const float4*)&Qp[(size_t)(q0 + lr + rr) * DK_ + lc];
        float4 qs = make_float4(q.x * 0.125f, q.y * 0.125f, q.z * 0.125f, q.w * 0.125f);
        *(float4*)&Qs[lr + rr][lc] = qs;
    }

    float m_i[4], l_i[4], Oacc[4][4];
#pragma unroll
    for (int i = 0; i < 4; i++) {
        m_i[i] = -1e30f; l_i[i] = 0.0f;
#pragma unroll
        for (int j = 0; j < 4; j++) Oacc[i][j] = 0.0f;
    }

    for (int kt = 0; kt <= qt; kt++) {
        const int kv0 = kt * 64;
        __syncthreads();   // previous iteration's reads of KPs/Vs complete

        // K tile -> KPs[k][c] (transposed in smem; stores hit distinct banks)
#pragma unroll
        for (int rr = 0; rr < 4; rr++) {
            const int kb = rr * 16 + kq * 4;
            float4 kv4 = *(const float4*)&Kp[(size_t)(kv0 + kc) * DK_ + kb];
            KPs[kb + 0][kc] = kv4.x;
            KPs[kb + 1][kc] = kv4.y;
            KPs[kb + 2][kc] = kv4.z;
            KPs[kb + 3][kc] = kv4.w;
        }
        // V tile -> Vs[c][d] (direct copy)
#pragma unroll
        for (int rr = 0; rr < 64; rr += 16) {
            float4 v = *(const float4*)&Vp[(size_t)(kv0 + lr + rr) * DK_ + lc];
            *(float4*)&Vs[lr + rr][lc] = v;
        }
        __syncthreads();   // tiles ready

        // S = Q * K^T (scale folded into Q)
        float Sv[4][4];
#pragma unroll
        for (int i = 0; i < 4; i++)
#pragma unroll
            for (int j = 0; j < 4; j++) Sv[i][j] = 0.0f;

#pragma unroll 16
        for (int kk = 0; kk < 64; kk++) {
            float q0r = Qs[ty * 4 + 0][kk];
            float q1r = Qs[ty * 4 + 1][kk];
            float q2r = Qs[ty * 4 + 2][kk];
            float q3r = Qs[ty * 4 + 3][kk];
            float4 kv = *(const float4*)&KPs[kk][tx * 4];
            Sv[0][0] += q0r * kv.x; Sv[0][1] += q0r * kv.y; Sv[0][2] += q0r * kv.z; Sv[0][3] += q0r * kv.w;
            Sv[1][0] += q1r * kv.x; Sv[1][1] += q1r * kv.y; Sv[1][2] += q1r * kv.z; Sv[1][3] += q1r * kv.w;
            Sv[2][0] += q2r * kv.x; Sv[2][1] += q2r * kv.y; Sv[2][2] += q2r * kv.z; Sv[2][3] += q2r * kv.w;
            Sv[3][0] += q3r * kv.x; Sv[3][1] += q3r * kv.y; Sv[3][2] += q3r * kv.z; Sv[3][3] += q3r * kv.w;
        }

        // Causal mask on the diagonal tile
        if (kt == qt) {
#pragma unroll
            for (int i = 0; i < 4; i++)
#pragma unroll
                for (int j = 0; j < 4; j++)
                    if (tx * 4 + j > ty * 4 + i) Sv[i][j] = -1e30f;
        }

        __syncthreads();   // done reading KPs as K; safe to overwrite with P

        // Online softmax (row groups = 16 lanes sharing ty)
        float Pv[4][4];
#pragma unroll
        for (int i = 0; i < 4; i++) {
            float mx = fmaxf(fmaxf(Sv[i][0], Sv[i][1]), fmaxf(Sv[i][2], Sv[i][3]));
#pragma unroll
            for (int off = 8; off >= 1; off >>= 1)
                mx = fmaxf(mx, __shfl_xor_sync(FULL, mx, off));
            float mn   = fmaxf(m_i[i], mx);
            float corr = __expf(m_i[i] - mn);
            float rs = 0.0f;
#pragma unroll
            for (int j = 0; j < 4; j++) {
                float p = __expf(Sv[i][j] - mn);
                Pv[i][j] = p;
                rs += p;
            }
#pragma unroll
            for (int off = 8; off >= 1; off >>= 1)
                rs += __shfl_xor_sync(FULL, rs, off);
            l_i[i] = l_i[i] * corr + rs;
            m_i[i] = mn;
#pragma unroll
            for (int j = 0; j < 4; j++) Oacc[i][j] *= corr;
        }

        // Store P into the KPs buffer as [r][c]
#pragma unroll
        for (int i = 0; i < 4; i++) {
            float4 p4 = make_float4(Pv[i][0], Pv[i][1], Pv[i][2], Pv[i][3]);
            *(float4*)&KPs[ty * 4 + i][tx * 4] = p4;
        }
        __syncthreads();   // P ready

        // O += P * V
#pragma unroll 16
        for (int kv = 0; kv < 64; kv++) {
            float p0 = KPs[ty * 4 + 0][kv];
            float p1 = KPs[ty * 4 + 1][kv];
            float p2 = KPs[ty * 4 + 2][kv];
            float p3 = KPs[ty * 4 + 3][kv];
            float4 vv = *(const float4*)&Vs[kv][tx * 4];
            Oacc[0][0] += p0 * vv.x; Oacc[0][1] += p0 * vv.y; Oacc[0][2] += p0 * vv.z; Oacc[0][3] += p0 * vv.w;
            Oacc[1][0] += p1 * vv.x; Oacc[1][1] += p1 * vv.y; Oacc[1][2] += p1 * vv.z; Oacc[1][3] += p1 * vv.w;
            Oacc[2][0] += p2 * vv.x; Oacc[2][1] += p2 * vv.y; Oacc[2][2] += p2 * vv.z; Oacc[2][3] += p2 * vv.w;
            Oacc[3][0] += p3 * vv.x; Oacc[3][1] += p3 * vv.y; Oacc[3][2] += p3 * vv.z; Oacc[3][3] += p3 * vv.w;
        }
    }

    // Normalize and write O
#pragma unroll
    for (int i = 0; i < 4; i++) {
        float inv = 1.0f / l_i[i];
        float4 o = make_float4(Oacc[i][0] * inv, Oacc[i][1] * inv,
                               Oacc[i][2] * inv, Oacc[i][3] * inv);
        *(float4*)&Op[(size_t)(q0 + ty * 4 + i) * DK_ + tx * 4] = o;
    }
}

// ---------------------------------------------------------------------------
// Kernel 3: output projection.
//   out[m][n] = sum_j concat[m][j] * Wo[j][n] + bo[n]
//   concat[m][j] = g_O[((b*H + j>>6)*S + s)*DK + (j&63)],  m = b*S + s
// ---------------------------------------------------------------------------
__global__ __launch_bounds__(256) void out_gemm(
    const float* __restrict__ Wo, const float* __restrict__ bo,
    float* __restrict__ out)
{
    __shared__ float As[16][128];
    __shared__ float Bs[16][128];

    const int tid  = threadIdx.x;
    const int ty   = tid >> 4;
    const int tx   = tid & 15;
    const int m0   = blockIdx.x * 128;
    const int n0   = blockIdx.y * 128;
    const int bb   = m0 >> 11;

    const int arow = tid >> 2;
    const int acol = (tid & 3) << 2;
    const int brow = tid >> 5;
    const int bcol = (tid & 31) << 2;

    const int s_a0 = (m0 & 2047) + arow;

    float acc[8][8];
#pragma unroll
    for (int i = 0; i < 8; i++)
#pragma unroll
        for (int j = 0; j < 8; j++) acc[i][j] = 0.0f;

    for (int k0 = 0; k0 < H_ * DK_; k0 += 16) {
        // 16-wide j-chunk never crosses a head boundary (16 | 64)
        const int h   = k0 >> 6;
        const int kin = (k0 & 63) + acol;
        const float* abase = g_O + (size_t)(bb * H_ + h) * S_ * DK_;
        float4 a0 = *(const float4*)&abase[(size_t)(s_a0)      * DK_ + kin];
        float4 a1 = *(const float4*)&abase[(size_t)(s_a0 + 64) * DK_ + kin];
        float4 b0 = *(const float4*)&Wo[(size_t)(k0 + brow)     * D_ + n0 + bcol];
        float4 b1 = *(const float4*)&Wo[(size_t)(k0 + brow + 8) * D_ + n0 + bcol];

        __syncthreads();
        As[acol + 0][arow] = a0.x; As[acol + 1][arow] = a0.y;
        As[acol + 2][arow] = a0.z; As[acol + 3][arow] = a0.w;
        As[acol + 0][arow + 64] = a1.x; As[acol + 1][arow + 64] = a1.y;
        As[acol + 2][arow + 64] = a1.z; As[acol + 3][arow + 64] = a1.w;
        *(float4*)&Bs[brow][bcol]     = b0;
        *(float4*)&Bs[brow + 8][bcol] = b1;
        __syncthreads();

#pragma unroll
        for (int kk = 0; kk < 16; kk++) {
            float4 av0 = *(const float4*)&As[kk][ty * 8];
            float4 av1 = *(const float4*)&As[kk][ty * 8 + 4];
            float4 bv0 = *(const float4*)&Bs[kk][tx * 8];
            float4 bv1 = *(const float4*)&Bs[kk][tx * 8 + 4];
            float ar[8] = {av0.x, av0.y, av0.z, av0.w, av1.x, av1.y, av1.z, av1.w};
            float br[8] = {bv0.x, bv0.y, bv0.z, bv0.w, bv1.x, bv1.y, bv1.z, bv1.w};
#pragma unroll
            for (int i = 0; i < 8; i++)
#pragma unroll
                for (int j = 0; j < 8; j++)
                    acc[i][j] += ar[i] * br[j];
        }
    }

    const int ncol = n0 + tx * 8;
    float bz[8];
#pragma unroll
    for (int j = 0; j < 8; j++) bz[j] = bo[ncol + j];

#pragma unroll
    for (int i = 0; i < 8; i++) {
        const int m = m0 + ty * 8 + i;
        float* orow = out + (size_t)m * D_ + ncol;
        float4 o0 = make_float4(acc[i][0] + bz[0], acc[i][1] + bz[1],
                                acc[i][2] + bz[2], acc[i][3] + bz[3]);
        float4 o1 = make_float4(acc[i][4] + bz[4], acc[i][5] + bz[5],
                                acc[i][6] + bz[6], acc[i][7] + bz[7]);
        *(float4*)&orow[0] = o0;
        *(float4*)&orow[4] = o1;
    }
}

// ---------------------------------------------------------------------------
extern "C" void kernel_launch(void* const* d_in, const int* in_sizes, int n_in,
                              void* d_out, int out_size)
{
    const float* x  = (const float*)d_in[0];
    // d_in[1] = encoder_output: unused (reference is self-attention path)
    const float* Wq = (const float*)d_in[2];
    const float* bq = (const float*)d_in[3];
    const float* Wk = (const float*)d_in[4];
    const float* bk = (const float*)d_in[5];
    const float* Wv = (const float*)d_in[6];
    const float* bv = (const float*)d_in[7];
    const float* Wo = (const float*)d_in[8];
    const float* bo = (const float*)d_in[9];
    float* out = (float*)d_out;

    dim3 gq(M_ / 128, (H_ * DK_) / 128, 3);   // 64 x 8 x 3
    qkv_gemm<<<gq, 256>>>(x, Wq, bq, Wk, bk, Wv, bv);

    attn_kernel<<<dim3(S_ / 64, B_ * H_), 256>>>();

    out_gemm<<<dim3(M_ / 128, D_ / 128), 256>>>(Wo, bo, out);
}

// round 3
// speedup vs baseline: 1.2770x; 1.2770x over previous
#include <cuda_runtime.h>
#include <cstdint>

#define B_  4
#define S_  2048
#define D_  1024
#define H_  16
#define DK_ 64
#define M_  (B_ * S_)                    // 8192
#define QKV_ELEMS (B_ * H_ * S_ * DK_)   // 8388608

// Scratch (device globals; no runtime allocation)
__device__ float g_Q[QKV_ELEMS];
__device__ float g_K[QKV_ELEMS];
__device__ float g_V[QKV_ELEMS];
__device__ float g_O[QKV_ELEMS];
__device__ float g_WT[3 * D_ * D_];      // W^T for Q,K,V: [z][j][d]
__device__ float g_WoT[D_ * D_];         // Wo^T: [n][j]

// ---------------------------------------------------------------------------
// Helpers (base-ISA only: mma.sync + cp.async; NO tcgen05/mbarrier)
// ---------------------------------------------------------------------------
__device__ __forceinline__ uint32_t smem_u32(const void* p) {
    uint32_t a;
    asm("{ .reg .u64 t; cvta.to.shared.u64 t, %1; cvt.u32.u64 %0, t; }"
        : "=r"(a) : "l"(p));
    return a;
}
__device__ __forceinline__ uint32_t cvt_tf32(float v) {
    uint32_t r;
    asm("cvt.rna.tf32.f32 %0, %1;" : "=r"(r) : "f"(v));
    return r;
}
__device__ __forceinline__ void split_tf32(float v, uint32_t& hi, uint32_t& lo) {
    hi = cvt_tf32(v);
    lo = cvt_tf32(v - __uint_as_float(hi));
}
// D += A*B, m16n8k8 tf32
__device__ __forceinline__ void mma8(float* c,
                                     uint32_t a0, uint32_t a1, uint32_t a2, uint32_t a3,
                                     uint32_t b0, uint32_t b1) {
    asm volatile(
        "mma.sync.aligned.m16n8k8.row.col.f32.tf32.tf32.f32 "
        "{%0,%1,%2,%3}, {%4,%5,%6,%7}, {%8,%9}, {%0,%1,%2,%3};"
        : "+f"(c[0]), "+f"(c[1]), "+f"(c[2]), "+f"(c[3])
        : "r"(a0), "r"(a1), "r"(a2), "r"(a3), "r"(b0), "r"(b1));
}
__device__ __forceinline__ void cp16(uint32_t saddr, const void* gptr) {
    asm volatile("cp.async.cg.shared.global [%0], [%1], 16;"
                 :: "r"(saddr), "l"(gptr) : "memory");
}
#define CP_COMMIT() asm volatile("cp.async.commit_group;" ::: "memory")
#define CP_WAIT(n)  asm volatile("cp.async.wait_group %0;" :: "n"(n) : "memory")

// ---------------------------------------------------------------------------
// Weight transposes (once per launch, ~15us)
// ---------------------------------------------------------------------------
__global__ void transpose_qkv(const float* __restrict__ Wq,
                              const float* __restrict__ Wk,
                              const float* __restrict__ Wv)
{
    __shared__ float t[32][33];
    const int z = blockIdx.z >> 4;
    const int h = blockIdx.z & 15;
    const float* in = (z == 0 ? Wq : z == 1 ? Wk : Wv) + (size_t)h * D_ * DK_;
    const int j0 = blockIdx.x * 32;
    const int d0 = blockIdx.y * 32;
    const int tx = threadIdx.x, ty = threadIdx.y;
#pragma unroll
    for (int q = 0; q < 4; q++)
        t[ty + 8 * q][tx] = in[(size_t)(d0 + ty + 8 * q) * DK_ + j0 + tx];
    __syncthreads();
    float* outp = g_WT + (size_t)z * D_ * D_ + (size_t)(h * 64 + j0) * D_ + d0;
#pragma unroll
    for (int q = 0; q < 4; q++)
        outp[(size_t)(ty + 8 * q) * D_ + tx] = t[tx][ty + 8 * q];
}

__global__ void transpose_wo(const float* __restrict__ Wo)
{
    __shared__ float t[32][33];
    const int n0 = blockIdx.x * 32;
    const int j0 = blockIdx.y * 32;
    const int tx = threadIdx.x, ty = threadIdx.y;
#pragma unroll
    for (int q = 0; q < 4; q++)
        t[ty + 8 * q][tx] = Wo[(size_t)(j0 + ty + 8 * q) * D_ + n0 + tx];
    __syncthreads();
#pragma unroll
    for (int q = 0; q < 4; q++)
        g_WoT[(size_t)(n0 + ty + 8 * q) * D_ + j0 + tx] = t[tx][ty + 8 * q];
}

// ---------------------------------------------------------------------------
// GEMM config: 128x128x32 CTA tile, 8 warps (2x4), warp tile 64x32.
// smem: fp32 A[128][36], B[128][36] per stage, double buffered.
// ---------------------------------------------------------------------------
#define GPAD 36
#define GEMM_SMEM (2 * 2 * 128 * GPAD * 4)   // 73728 B

// compute one BK=32 chunk from stage smem into c[4][4][4]
__device__ __forceinline__ void gemm_chunk(const float (*As)[GPAD], const float (*Bs)[GPAD],
                                           int wm, int wn, int g, int t,
                                           float c[4][4][4])
{
#pragma unroll
    for (int ks = 0; ks < 4; ks++) {
        const int kc = ks * 8;
        uint32_t ah[4][4], al[4][4];
#pragma unroll
        for (int mf = 0; mf < 4; mf++) {
            const int r = wm * 64 + mf * 16;
            split_tf32(As[r + g][kc + t],          ah[mf][0], al[mf][0]);
            split_tf32(As[r + g + 8][kc + t],      ah[mf][1], al[mf][1]);
            split_tf32(As[r + g][kc + t + 4],      ah[mf][2], al[mf][2]);
            split_tf32(As[r + g + 8][kc + t + 4],  ah[mf][3], al[mf][3]);
        }
        uint32_t bh[4][2], bl[4][2];
#pragma unroll
        for (int nf = 0; nf < 4; nf++) {
            const int n = wn * 32 + nf * 8;
            split_tf32(Bs[n + g][kc + t],     bh[nf][0], bl[nf][0]);
            split_tf32(Bs[n + g][kc + t + 4], bh[nf][1], bl[nf][1]);
        }
#pragma unroll
        for (int mf = 0; mf < 4; mf++)
#pragma unroll
            for (int nf = 0; nf < 4; nf++) {
                mma8(c[mf][nf], ah[mf][0], ah[mf][1], ah[mf][2], ah[mf][3],
                     bh[nf][0], bh[nf][1]);
                mma8(c[mf][nf], ah[mf][0], ah[mf][1], ah[mf][2], ah[mf][3],
                     bl[nf][0], bl[nf][1]);
                mma8(c[mf][nf], al[mf][0], al[mf][1], al[mf][2], al[mf][3],
                     bh[nf][0], bh[nf][1]);
            }
    }
}

// ---------------------------------------------------------------------------
// QKV projection via mma.sync tf32x3
// ---------------------------------------------------------------------------
__global__ __launch_bounds__(256) void qkv_mma(
    const float* __restrict__ x,
    const float* __restrict__ bq, const float* __restrict__ bk,
    const float* __restrict__ bv)
{
    extern __shared__ float sm[];
    float (*Asm)[GPAD] = (float(*)[GPAD])sm;                  // [2*128][GPAD] stages
    float (*Bsm)[GPAD] = (float(*)[GPAD])(sm + 2 * 128 * GPAD);

    const int tid = threadIdx.x;
    const int wid = tid >> 5;
    const int lane = tid & 31;
    const int g = lane >> 2, t = lane & 3;
    const int wm = wid >> 2, wn = wid & 3;
    const int m0 = blockIdx.x * 128;
    const int n0 = blockIdx.y * 128;
    const int z  = blockIdx.z;

    const float* Bt = g_WT + (size_t)z * D_ * D_;
    float* outp = (z == 0) ? g_Q : (z == 1) ? g_K : g_V;
    const float* bias = (z == 0) ? bq : (z == 1) ? bk : bv;

    const int lr = tid >> 3;          // 0..31 (x4 passes -> 128 rows)
    const int lc = (tid & 7) * 4;     // 0..28

    const uint32_t aB = smem_u32(sm);
    const uint32_t bB = aB + 2 * 128 * GPAD * 4;

    // prologue: chunk 0 -> stage 0
#pragma unroll
    for (int i = 0; i < 4; i++) {
        const int r = lr + i * 32;
        cp16(aB + (uint32_t)((r) * GPAD + lc) * 4, &x [(size_t)(m0 + r) * D_ + lc]);
        cp16(bB + (uint32_t)((r) * GPAD + lc) * 4, &Bt[(size_t)(n0 + r) * D_ + lc]);
    }
    CP_COMMIT();

    float c[4][4][4];
#pragma unroll
    for (int a = 0; a < 4; a++)
#pragma unroll
        for (int b = 0; b < 4; b++)
#pragma unroll
            for (int q = 0; q < 4; q++) c[a][b][q] = 0.0f;

    for (int ch = 0; ch < 32; ch++) {
        const int s = ch & 1;
        if (ch + 1 < 32) {
            const int k0 = (ch + 1) * 32;
            const uint32_t so = (uint32_t)((ch + 1) & 1) * 128 * GPAD * 4;
#pragma unroll
            for (int i = 0; i < 4; i++) {
                const int r = lr + i * 32;
                cp16(aB + so + (uint32_t)(r * GPAD + lc) * 4,
                     &x [(size_t)(m0 + r) * D_ + k0 + lc]);
                cp16(bB + so + (uint32_t)(r * GPAD + lc) * 4,
                     &Bt[(size_t)(n0 + r) * D_ + k0 + lc]);
            }
            CP_COMMIT();
            CP_WAIT(1);
        } else {
            CP_WAIT(0);
        }
        __syncthreads();
        gemm_chunk(&Asm[s * 128], &Bsm[s * 128], wm, wn, g, t, c);
        __syncthreads();
    }

    // epilogue: scatter to [B,H,S,DK] + bias
#pragma unroll
    for (int mf = 0; mf < 4; mf++) {
#pragma unroll
        for (int nf = 0; nf < 4; nf++) {
            const int j = n0 + wn * 32 + nf * 8 + 2 * t;
            const int head = j >> 6, kin = j & 63;
            const float bz0 = bias[j], bz1 = bias[j + 1];
#pragma unroll
            for (int rr = 0; rr < 2; rr++) {
                const int m = m0 + wm * 64 + mf * 16 + g + rr * 8;
                const int b = m >> 11, sidx = m & 2047;
                float* p = outp + ((size_t)(b * H_ + head) * S_ + sidx) * DK_ + kin;
                float2 o = make_float2(c[mf][nf][rr * 2] + bz0,
                                       c[mf][nf][rr * 2 + 1] + bz1);
                *(float2*)p = o;
            }
        }
    }
}

// ---------------------------------------------------------------------------
// Output projection via mma.sync tf32x3
// ---------------------------------------------------------------------------
__global__ __launch_bounds__(256) void out_mma(
    const float* __restrict__ bo, float* __restrict__ out)
{
    extern __shared__ float sm[];
    float (*Asm)[GPAD] = (float(*)[GPAD])sm;
    float (*Bsm)[GPAD] = (float(*)[GPAD])(sm + 2 * 128 * GPAD);

    const int tid = threadIdx.x;
    const int wid = tid >> 5;
    const int lane = tid & 31;
    const int g = lane >> 2, t = lane & 3;
    const int wm = wid >> 2, wn = wid & 3;
    const int m0 = blockIdx.x * 128;
    const int n0 = blockIdx.y * 128;
    const int bb = m0 >> 11;
    const int sbase = m0 & 2047;

    const int lr = tid >> 3;
    const int lc = (tid & 7) * 4;

    const uint32_t aB = smem_u32(sm);
    const uint32_t bB = aB + 2 * 128 * GPAD * 4;

    // gather source for A chunk ch: head = (ch*32)>>6, kin = (ch*32)&63
#pragma unroll
    for (int i = 0; i < 4; i++) {
        const int r = lr + i * 32;
        const float* src = g_O + ((size_t)(bb * H_ + 0) * S_ + sbase + r) * DK_ + 0 + lc;
        cp16(aB + (uint32_t)(r * GPAD + lc) * 4, src);
        cp16(bB + (uint32_t)(r * GPAD + lc) * 4, &g_WoT[(size_t)(n0 + r) * D_ + lc]);
    }
    CP_COMMIT();

    float c[4][4][4];
#pragma unroll
    for (int a = 0; a < 4; a++)
#pragma unroll
        for (int b = 0; b < 4; b++)
#pragma unroll
            for (int q = 0; q < 4; q++) c[a][b][q] = 0.0f;

    for (int ch = 0; ch < 32; ch++) {
        const int s = ch & 1;
        if (ch + 1 < 32) {
            const int k0 = (ch + 1) * 32;
            const int head = k0 >> 6, kin = k0 & 63;
            const uint32_t so = (uint32_t)((ch + 1) & 1) * 128 * GPAD * 4;
#pragma unroll
            for (int i = 0; i < 4; i++) {
                const int r = lr + i * 32;
                const float* src = g_O +
                    ((size_t)(bb * H_ + head) * S_ + sbase + r) * DK_ + kin + lc;
                cp16(aB + so + (uint32_t)(r * GPAD + lc) * 4, src);
                cp16(bB + so + (uint32_t)(r * GPAD + lc) * 4,
                     &g_WoT[(size_t)(n0 + r) * D_ + k0 + lc]);
            }
            CP_COMMIT();
            CP_WAIT(1);
        } else {
            CP_WAIT(0);
        }
        __syncthreads();
        gemm_chunk(&Asm[s * 128], &Bsm[s * 128], wm, wn, g, t, c);
        __syncthreads();
    }

#pragma unroll
    for (int mf = 0; mf < 4; mf++) {
#pragma unroll
        for (int nf = 0; nf < 4; nf++) {
            const int j = n0 + wn * 32 + nf * 8 + 2 * t;
            const float bz0 = bo[j], bz1 = bo[j + 1];
#pragma unroll
            for (int rr = 0; rr < 2; rr++) {
                const int m = m0 + wm * 64 + mf * 16 + g + rr * 8;
                float2 o = make_float2(c[mf][nf][rr * 2] + bz0,
                                       c[mf][nf][rr * 2 + 1] + bz1);
                *(float2*)&out[(size_t)m * D_ + j] = o;
            }
        }
    }
}

// ---------------------------------------------------------------------------
// Causal flash attention via mma.sync tf32x3.
// 128 threads (4 warps), q-tile 64 (16 rows/warp), kv-tile 64.
// Smem: Qs/Ks/Vt/Ps, each [64][68] fp32 (dynamic, 69632 B).
// ---------------------------------------------------------------------------
#define APAD 68
#define ATTN_SMEM (4 * 64 * APAD * 4)

__global__ __launch_bounds__(128) void attn_mma()
{
    extern __shared__ float sm[];
    float (*Qs)[APAD] = (float(*)[APAD])sm;
    float (*Ks)[APAD] = Qs + 64;
    float (*Vt)[APAD] = Ks + 64;
    float (*Ps)[APAD] = Vt + 64;

    const int qt = blockIdx.x;
    const int bh = blockIdx.y;
    const float* Qp = g_Q + (size_t)bh * S_ * DK_;
    const float* Kp = g_K + (size_t)bh * S_ * DK_;
    const float* Vp = g_V + (size_t)bh * S_ * DK_;
    float*       Op = g_O + (size_t)bh * S_ * DK_;

    const int tid = threadIdx.x;
    const int wid = tid >> 5;
    const int lane = tid & 31;
    const int g = lane >> 2, t = lane & 3;
    const int mrow = wid * 16;
    const int q0 = qt * 64;

    // Q load once, pre-scaled
    {
        const int r = tid >> 4;            // 0..7 (x8)
        const int c4 = (tid & 15) * 4;
#pragma unroll
        for (int i = 0; i < 8; i++) {
            float4 q = *(const float4*)&Qp[(size_t)(q0 + r + i * 8) * DK_ + c4];
            Qs[r + i * 8][c4 + 0] = q.x * 0.125f;
            Qs[r + i * 8][c4 + 1] = q.y * 0.125f;
            Qs[r + i * 8][c4 + 2] = q.z * 0.125f;
            Qs[r + i * 8][c4 + 3] = q.w * 0.125f;
        }
    }

    float cO[8][4];
#pragma unroll
    for (int nf = 0; nf < 8; nf++)
#pragma unroll
        for (int q = 0; q < 4; q++) cO[nf][q] = 0.0f;
    float m0v = -1e30f, m1v = -1e30f, l0 = 0.0f, l1 = 0.0f;

    const int lrk = tid >> 4;          // K-tile load rows
    const int lck = (tid & 15) * 4;
    const int vc = tid & 63;           // V transposed column
    const int vq = tid >> 6;           // 0..1

    for (int kt = 0; kt <= qt; kt++) {
        const int kv0 = kt * 64;
        __syncthreads();
        // K tile direct copy [kv][d]
#pragma unroll
        for (int i = 0; i < 8; i++) {
            float4 k = *(const float4*)&Kp[(size_t)(kv0 + lrk + i * 8) * DK_ + lck];
            *(float4*)&Ks[lrk + i * 8][lck] = k;
        }
        // V transposed [d][kv]
#pragma unroll
        for (int i = 0; i < 8; i++) {
            const int kb = i * 8 + vq * 4;
            float4 v = *(const float4*)&Vp[(size_t)(kv0 + vc) * DK_ + kb];
            Vt[kb + 0][vc] = v.x;
            Vt[kb + 1][vc] = v.y;
            Vt[kb + 2][vc] = v.z;
            Vt[kb + 3][vc] = v.w;
        }
        __syncthreads();

        // S = Q K^T (x3)
        float cS[8][4];
#pragma unroll
        for (int nf = 0; nf < 8; nf++)
#pragma unroll
            for (int q = 0; q < 4; q++) cS[nf][q] = 0.0f;

#pragma unroll
        for (int ks = 0; ks < 8; ks++) {
            const int kc = ks * 8;
            uint32_t ah[4], al[4];
            split_tf32(Qs[mrow + g][kc + t],         ah[0], al[0]);
            split_tf32(Qs[mrow + g + 8][kc + t],     ah[1], al[1]);
            split_tf32(Qs[mrow + g][kc + t + 4],     ah[2], al[2]);
            split_tf32(Qs[mrow + g + 8][kc + t + 4], ah[3], al[3]);
#pragma unroll
            for (int nf = 0; nf < 8; nf++) {
                uint32_t bh0, bl0, bh1, bl1;
                split_tf32(Ks[nf * 8 + g][kc + t],     bh0, bl0);
                split_tf32(Ks[nf * 8 + g][kc + t + 4], bh1, bl1);
                mma8(cS[nf], ah[0], ah[1], ah[2], ah[3], bh0, bh1);
                mma8(cS[nf], ah[0], ah[1], ah[2], ah[3], bl0, bl1);
                mma8(cS[nf], al[0], al[1], al[2], al[3], bh0, bh1);
            }
        }

        // causal mask on diagonal tile (local indices comparable)
        if (kt == qt) {
#pragma unroll
            for (int nf = 0; nf < 8; nf++) {
                const int col = nf * 8 + 2 * t;
                const int r0 = mrow + g, r1 = mrow + g + 8;
                if (col     > r0) cS[nf][0] = -1e30f;
                if (col + 1 > r0) cS[nf][1] = -1e30f;
                if (col     > r1) cS[nf][2] = -1e30f;
                if (col + 1 > r1) cS[nf][3] = -1e30f;
            }
        }

        // online softmax (rows g and g+8; 4 lanes per row share t)
        float mx0 = -1e30f, mx1 = -1e30f;
#pragma unroll
        for (int nf = 0; nf < 8; nf++) {
            mx0 = fmaxf(mx0, fmaxf(cS[nf][0], cS[nf][1]));
            mx1 = fmaxf(mx1, fmaxf(cS[nf][2], cS[nf][3]));
        }
        mx0 = fmaxf(mx0, __shfl_xor_sync(0xffffffffu, mx0, 1));
        mx0 = fmaxf(mx0, __shfl_xor_sync(0xffffffffu, mx0, 2));
        mx1 = fmaxf(mx1, __shfl_xor_sync(0xffffffffu, mx1, 1));
        mx1 = fmaxf(mx1, __shfl_xor_sync(0xffffffffu, mx1, 2));
        const float mn0 = fmaxf(m0v, mx0), mn1 = fmaxf(m1v, mx1);
        const float corr0 = __expf(m0v - mn0), corr1 = __expf(m1v - mn1);
        float rs0 = 0.0f, rs1 = 0.0f;
#pragma unroll
        for (int nf = 0; nf < 8; nf++) {
            const float p0 = __expf(cS[nf][0] - mn0);
            const float p1 = __expf(cS[nf][1] - mn0);
            const float p2 = __expf(cS[nf][2] - mn1);
            const float p3 = __expf(cS[nf][3] - mn1);
            rs0 += p0 + p1; rs1 += p2 + p3;
            *(float2*)&Ps[mrow + g][nf * 8 + 2 * t]     = make_float2(p0, p1);
            *(float2*)&Ps[mrow + g + 8][nf * 8 + 2 * t] = make_float2(p2, p3);
        }
        rs0 += __shfl_xor_sync(0xffffffffu, rs0, 1);
        rs0 += __shfl_xor_sync(0xffffffffu, rs0, 2);
        rs1 += __shfl_xor_sync(0xffffffffu, rs1, 1);
        rs1 += __shfl_xor_sync(0xffffffffu, rs1, 2);
        l0 = l0 * corr0 + rs0; l1 = l1 * corr1 + rs1;
        m0v = mn0; m1v = mn1;
#pragma unroll
        for (int nf = 0; nf < 8; nf++) {
            cO[nf][0] *= corr0; cO[nf][1] *= corr0;
            cO[nf][2] *= corr1; cO[nf][3] *= corr1;
        }
        __syncwarp();

        // O += P V (x3): A = Ps[m][kv], B = Vt[d][kv]
#pragma unroll
        for (int ks = 0; ks < 8; ks++) {
            const int kc = ks * 8;
            uint32_t ah[4], al[4];
            split_tf32(Ps[mrow + g][kc + t],         ah[0], al[0]);
            split_tf32(Ps[mrow + g + 8][kc + t],     ah[1], al[1]);
            split_tf32(Ps[mrow + g][kc + t + 4],     ah[2], al[2]);
            split_tf32(Ps[mrow + g + 8][kc + t + 4], ah[3], al[3]);
#pragma unroll
            for (int nf = 0; nf < 8; nf++) {
                uint32_t bh0, bl0, bh1, bl1;
                split_tf32(Vt[nf * 8 + g][kc + t],     bh0, bl0);
                split_tf32(Vt[nf * 8 + g][kc + t + 4], bh1, bl1);
                mma8(cO[nf], ah[0], ah[1], ah[2], ah[3], bh0, bh1);
                mma8(cO[nf], ah[0], ah[1], ah[2], ah[3], bl0, bl1);
                mma8(cO[nf], al[0], al[1], al[2], al[3], bh0, bh1);
            }
        }
    }

    // normalize + store O
    const float inv0 = 1.0f / l0, inv1 = 1.0f / l1;
#pragma unroll
    for (int nf = 0; nf < 8; nf++) {
        const int col = nf * 8 + 2 * t;
        *(float2*)&Op[(size_t)(q0 + mrow + g) * DK_ + col] =
            make_float2(cO[nf][0] * inv0, cO[nf][1] * inv0);
        *(float2*)&Op[(size_t)(q0 + mrow + g + 8) * DK_ + col] =
            make_float2(cO[nf][2] * inv1, cO[nf][3] * inv1);
    }
}

// ---------------------------------------------------------------------------
extern "C" void kernel_launch(void* const* d_in, const int* in_sizes, int n_in,
                              void* d_out, int out_size)
{
    const float* x  = (const float*)d_in[0];
    const float* Wq = (const float*)d_in[2];
    const float* bq = (const float*)d_in[3];
    const float* Wk = (const float*)d_in[4];
    const float* bk = (const float*)d_in[5];
    const float* Wv = (const float*)d_in[6];
    const float* bv = (const float*)d_in[7];
    const float* Wo = (const float*)d_in[8];
    const float* bo = (const float*)d_in[9];
    float* out = (float*)d_out;

    cudaFuncSetAttribute(qkv_mma, cudaFuncAttributeMaxDynamicSharedMemorySize, GEMM_SMEM);
    cudaFuncSetAttribute(out_mma, cudaFuncAttributeMaxDynamicSharedMemorySize, GEMM_SMEM);
    cudaFuncSetAttribute(attn_mma, cudaFuncAttributeMaxDynamicSharedMemorySize, ATTN_SMEM);

    transpose_qkv<<<dim3(2, 32, 48), dim3(32, 8)>>>(Wq, Wk, Wv);
    transpose_wo<<<dim3(32, 32), dim3(32, 8)>>>(Wo);

    qkv_mma<<<dim3(M_ / 128, D_ / 128, 3), 256, GEMM_SMEM>>>(x, bq, bk, bv);

    attn_mma<<<dim3(S_ / 64, B_ * H_), 128, ATTN_SMEM>>>();

    out_mma<<<dim3(M_ / 128, D_ / 128), 256, GEMM_SMEM>>>(bo, out);
}

// round 5
// speedup vs baseline: 1.4667x; 1.1485x over previous
#include <cuda_runtime.h>
#include <cstdint>

#define B_  4
#define S_  2048
#define D_  1024
#define H_  16
#define DK_ 64
#define M_  (B_ * S_)                    // 8192
#define QKV_ELEMS (B_ * H_ * S_ * DK_)   // 8388608

// Scratch (device globals; no runtime allocation)
__device__ float g_Q[QKV_ELEMS];
__device__ float g_K[QKV_ELEMS];
__device__ float g_V[QKV_ELEMS];
__device__ float g_O[QKV_ELEMS];
__device__ float g_WT[3 * D_ * D_];      // W^T for Q,K,V: [z][j][d]
__device__ float g_WoT[D_ * D_];         // Wo^T: [n][j]

// ---------------------------------------------------------------------------
// Helpers (base-ISA only: mma.sync + cp.async)
// ---------------------------------------------------------------------------
__device__ __forceinline__ uint32_t smem_u32(const void* p) {
    uint32_t a;
    asm("{ .reg .u64 t; cvta.to.shared.u64 t, %1; cvt.u32.u64 %0, t; }"
        : "=r"(a) : "l"(p));
    return a;
}
__device__ __forceinline__ uint32_t cvt_tf32(float v) {
    uint32_t r;
    asm("cvt.rna.tf32.f32 %0, %1;" : "=r"(r) : "f"(v));
    return r;
}
// hi via cvt.rna; lo passed as raw fp32 bits (HMMA truncates low mantissa: 2^-22 noise)
__device__ __forceinline__ void split2(float v, uint32_t& hi, uint32_t& lo) {
    hi = cvt_tf32(v);
    lo = __float_as_uint(v - __uint_as_float(hi));
}
// D += A*B, m16n8k8 tf32
__device__ __forceinline__ void mma8(float* c,
                                     uint32_t a0, uint32_t a1, uint32_t a2, uint32_t a3,
                                     uint32_t b0, uint32_t b1) {
    asm volatile(
        "mma.sync.aligned.m16n8k8.row.col.f32.tf32.tf32.f32 "
        "{%0,%1,%2,%3}, {%4,%5,%6,%7}, {%8,%9}, {%0,%1,%2,%3};"
        : "+f"(c[0]), "+f"(c[1]), "+f"(c[2]), "+f"(c[3])
        : "r"(a0), "r"(a1), "r"(a2), "r"(a3), "r"(b0), "r"(b1));
}
__device__ __forceinline__ void cp16(uint32_t saddr, const void* gptr) {
    asm volatile("cp.async.cg.shared.global [%0], [%1], 16;"
                 :: "r"(saddr), "l"(gptr) : "memory");
}
#define CP_COMMIT() asm volatile("cp.async.commit_group;" ::: "memory")
#define CP_WAIT(n)  asm volatile("cp.async.wait_group %0;" :: "n"(n) : "memory")

// ---------------------------------------------------------------------------
// Weight transposes (once per launch)
// ---------------------------------------------------------------------------
__global__ void transpose_qkv(const float* __restrict__ Wq,
                              const float* __restrict__ Wk,
                              const float* __restrict__ Wv)
{
    __shared__ float t[32][33];
    const int z = blockIdx.z >> 4;
    const int h = blockIdx.z & 15;
    const float* in = (z == 0 ? Wq : z == 1 ? Wk : Wv) + (size_t)h * D_ * DK_;
    const int j0 = blockIdx.x * 32;
    const int d0 = blockIdx.y * 32;
    const int tx = threadIdx.x, ty = threadIdx.y;
#pragma unroll
    for (int q = 0; q < 4; q++)
        t[ty + 8 * q][tx] = in[(size_t)(d0 + ty + 8 * q) * DK_ + j0 + tx];
    __syncthreads();
    float* outp = g_WT + (size_t)z * D_ * D_ + (size_t)(h * 64 + j0) * D_ + d0;
#pragma unroll
    for (int q = 0; q < 4; q++)
        outp[(size_t)(ty + 8 * q) * D_ + tx] = t[tx][ty + 8 * q];
}

__global__ void transpose_wo(const float* __restrict__ Wo)
{
    __shared__ float t[32][33];
    const int n0 = blockIdx.x * 32;
    const int j0 = blockIdx.y * 32;
    const int tx = threadIdx.x, ty = threadIdx.y;
#pragma unroll
    for (int q = 0; q < 4; q++)
        t[ty + 8 * q][tx] = Wo[(size_t)(j0 + ty + 8 * q) * D_ + n0 + tx];
    __syncthreads();
#pragma unroll
    for (int q = 0; q < 4; q++)
        g_WoT[(size_t)(n0 + ty + 8 * q) * D_ + j0 + tx] = t[tx][ty + 8 * q];
}

// ---------------------------------------------------------------------------
// GEMM: 128x128x32 CTA tile, 8 warps (2x4), warp tile 64x32, cp.async 2-stage.
// ---------------------------------------------------------------------------
#define GPAD 36
#define GEMM_SMEM (2 * 2 * 128 * GPAD * 4)   // 73728 B

__device__ __forceinline__ void gemm_chunk(const float (*As)[GPAD], const float (*Bs)[GPAD],
                                           int wm, int wn, int g, int t,
                                           float c[4][4][4])
{
#pragma unroll
    for (int ks = 0; ks < 4; ks++) {
        const int kc = ks * 8;
        uint32_t ah[4][4], al[4][4];
#pragma unroll
        for (int mf = 0; mf < 4; mf++) {
            const int r = wm * 64 + mf * 16;
            split2(As[r + g][kc + t],          ah[mf][0], al[mf][0]);
            split2(As[r + g + 8][kc + t],      ah[mf][1], al[mf][1]);
            split2(As[r + g][kc + t + 4],      ah[mf][2], al[mf][2]);
            split2(As[r + g + 8][kc + t + 4],  ah[mf][3], al[mf][3]);
        }
        uint32_t bh[4][2], bl[4][2];
#pragma unroll
        for (int nf = 0; nf < 4; nf++) {
            const int n = wn * 32 + nf * 8;
            split2(Bs[n + g][kc + t],     bh[nf][0], bl[nf][0]);
            split2(Bs[n + g][kc + t + 4], bh[nf][1], bl[nf][1]);
        }
#pragma unroll
        for (int mf = 0; mf < 4; mf++)
#pragma unroll
            for (int nf = 0; nf < 4; nf++) {
                mma8(c[mf][nf], ah[mf][0], ah[mf][1], ah[mf][2], ah[mf][3],
                     bh[nf][0], bh[nf][1]);
                mma8(c[mf][nf], ah[mf][0], ah[mf][1], ah[mf][2], ah[mf][3],
                     bl[nf][0], bl[nf][1]);
                mma8(c[mf][nf], al[mf][0], al[mf][1], al[mf][2], al[mf][3],
                     bh[nf][0], bh[nf][1]);
            }
    }
}

// ---------------------------------------------------------------------------
// QKV projection
// ---------------------------------------------------------------------------
__global__ __launch_bounds__(256) void qkv_mma(
    const float* __restrict__ x,
    const float* __restrict__ bq, const float* __restrict__ bk,
    const float* __restrict__ bv)
{
    extern __shared__ float sm[];
    float (*Asm)[GPAD] = (float(*)[GPAD])sm;
    float (*Bsm)[GPAD] = (float(*)[GPAD])(sm + 2 * 128 * GPAD);

    const int tid = threadIdx.x;
    const int wid = tid >> 5;
    const int lane = tid & 31;
    const int g = lane >> 2, t = lane & 3;
    const int wm = wid >> 2, wn = wid & 3;
    const int m0 = blockIdx.x * 128;
    const int n0 = blockIdx.y * 128;
    const int z  = blockIdx.z;

    const float* Bt = g_WT + (size_t)z * D_ * D_;
    float* outp = (z == 0) ? g_Q : (z == 1) ? g_K : g_V;
    const float* bias = (z == 0) ? bq : (z == 1) ? bk : bv;

    const int lr = tid >> 3;
    const int lc = (tid & 7) * 4;

    const uint32_t aB = smem_u32(sm);
    const uint32_t bB = aB + 2 * 128 * GPAD * 4;

#pragma unroll
    for (int i = 0; i < 4; i++) {
        const int r = lr + i * 32;
        cp16(aB + (uint32_t)(r * GPAD + lc) * 4, &x [(size_t)(m0 + r) * D_ + lc]);
        cp16(bB + (uint32_t)(r * GPAD + lc) * 4, &Bt[(size_t)(n0 + r) * D_ + lc]);
    }
    CP_COMMIT();

    float c[4][4][4];
#pragma unroll
    for (int a = 0; a < 4; a++)
#pragma unroll
        for (int b = 0; b < 4; b++)
#pragma unroll
            for (int q = 0; q < 4; q++) c[a][b][q] = 0.0f;

    for (int ch = 0; ch < 32; ch++) {
        const int s = ch & 1;
        if (ch + 1 < 32) {
            const int k0 = (ch + 1) * 32;
            const uint32_t so = (uint32_t)((ch + 1) & 1) * 128 * GPAD * 4;
#pragma unroll
            for (int i = 0; i < 4; i++) {
                const int r = lr + i * 32;
                cp16(aB + so + (uint32_t)(r * GPAD + lc) * 4,
                     &x [(size_t)(m0 + r) * D_ + k0 + lc]);
                cp16(bB + so + (uint32_t)(r * GPAD + lc) * 4,
                     &Bt[(size_t)(n0 + r) * D_ + k0 + lc]);
            }
            CP_COMMIT();
            CP_WAIT(1);
        } else {
            CP_WAIT(0);
        }
        __syncthreads();
        gemm_chunk(&Asm[s * 128], &Bsm[s * 128], wm, wn, g, t, c);
        __syncthreads();
    }

#pragma unroll
    for (int mf = 0; mf < 4; mf++) {
#pragma unroll
        for (int nf = 0; nf < 4; nf++) {
            const int j = n0 + wn * 32 + nf * 8 + 2 * t;
            const int head = j >> 6, kin = j & 63;
            const float bz0 = bias[j], bz1 = bias[j + 1];
#pragma unroll
            for (int rr = 0; rr < 2; rr++) {
                const int m = m0 + wm * 64 + mf * 16 + g + rr * 8;
                const int b = m >> 11, sidx = m & 2047;
                float* p = outp + ((size_t)(b * H_ + head) * S_ + sidx) * DK_ + kin;
                float2 o = make_float2(c[mf][nf][rr * 2] + bz0,
                                       c[mf][nf][rr * 2 + 1] + bz1);
                *(float2*)p = o;
            }
        }
    }
}

// ---------------------------------------------------------------------------
// Output projection
// ---------------------------------------------------------------------------
__global__ __launch_bounds__(256) void out_mma(
    const float* __restrict__ bo, float* __restrict__ out)
{
    extern __shared__ float sm[];
    float (*Asm)[GPAD] = (float(*)[GPAD])sm;
    float (*Bsm)[GPAD] = (float(*)[GPAD])(sm + 2 * 128 * GPAD);

    const int tid = threadIdx.x;
    const int wid = tid >> 5;
    const int lane = tid & 31;
    const int g = lane >> 2, t = lane & 3;
    const int wm = wid >> 2, wn = wid & 3;
    const int m0 = blockIdx.x * 128;
    const int n0 = blockIdx.y * 128;
    const int bb = m0 >> 11;
    const int sbase = m0 & 2047;

    const int lr = tid >> 3;
    const int lc = (tid & 7) * 4;

    const uint32_t aB = smem_u32(sm);
    const uint32_t bB = aB + 2 * 128 * GPAD * 4;

#pragma unroll
    for (int i = 0; i < 4; i++) {
        const int r = lr + i * 32;
        const float* src = g_O + ((size_t)(bb * H_ + 0) * S_ + sbase + r) * DK_ + lc;
        cp16(aB + (uint32_t)(r * GPAD + lc) * 4, src);
        cp16(bB + (uint32_t)(r * GPAD + lc) * 4, &g_WoT[(size_t)(n0 + r) * D_ + lc]);
    }
    CP_COMMIT();

    float c[4][4][4];
#pragma unroll
    for (int a = 0; a < 4; a++)
#pragma unroll
        for (int b = 0; b < 4; b++)
#pragma unroll
            for (int q = 0; q < 4; q++) c[a][b][q] = 0.0f;

    for (int ch = 0; ch < 32; ch++) {
        const int s = ch & 1;
        if (ch + 1 < 32) {
            const int k0 = (ch + 1) * 32;
            const int head = k0 >> 6, kin = k0 & 63;
            const uint32_t so = (uint32_t)((ch + 1) & 1) * 128 * GPAD * 4;
#pragma unroll
            for (int i = 0; i < 4; i++) {
                const int r = lr + i * 32;
                const float* src = g_O +
                    ((size_t)(bb * H_ + head) * S_ + sbase + r) * DK_ + kin + lc;
                cp16(aB + so + (uint32_t)(r * GPAD + lc) * 4, src);
                cp16(bB + so + (uint32_t)(r * GPAD + lc) * 4,
                     &g_WoT[(size_t)(n0 + r) * D_ + k0 + lc]);
            }
            CP_COMMIT();
            CP_WAIT(1);
        } else {
            CP_WAIT(0);
        }
        __syncthreads();
        gemm_chunk(&Asm[s * 128], &Bsm[s * 128], wm, wn, g, t, c);
        __syncthreads();
    }

#pragma unroll
    for (int mf = 0; mf < 4; mf++) {
#pragma unroll
        for (int nf = 0; nf < 4; nf++) {
            const int j = n0 + wn * 32 + nf * 8 + 2 * t;
            const float bz0 = bo[j], bz1 = bo[j + 1];
#pragma unroll
            for (int rr = 0; rr < 2; rr++) {
                const int m = m0 + wm * 64 + mf * 16 + g + rr * 8;
                float2 o = make_float2(c[mf][nf][rr * 2] + bz0,
                                       c[mf][nf][rr * 2 + 1] + bz1);
                *(float2*)&out[(size_t)m * D_ + j] = o;
            }
        }
    }
}

// ---------------------------------------------------------------------------
// Causal flash attention v2: 256 threads (8 warps), q-tile 128 (16 rows/warp),
// kv-tile 64. K/V split to hi/lo smem ONCE per tile (shared by all warps).
// Register prefetch of next K/V tile overlaps MMA phase. Reversed qb order.
// ---------------------------------------------------------------------------
#define APAD 68
#define ATTN_SMEM ((2 * 128 + 4 * 64) * APAD * 4)   // 139264 B

__global__ __launch_bounds__(256) void attn_mma2()
{
    extern __shared__ float sm[];
    float (*Qs)[APAD]  = (float(*)[APAD])sm;     // [128][APAD] fp32 (scaled)
    float (*Ps)[APAD]  = Qs + 128;               // [128][APAD] fp32
    float (*Khi)[APAD] = Ps + 128;               // [64][APAD] tf32-hi bits
    float (*Klo)[APAD] = Khi + 64;               // [64][APAD] residual fp32
    float (*Vhi)[APAD] = Klo + 64;               // [64][APAD] transposed [d][kv]
    float (*Vlo)[APAD] = Vhi + 64;

    const int qb = (int)(gridDim.x - 1) - (int)blockIdx.x;   // big tiles first
    const int bh = blockIdx.y;
    const float* Qp = g_Q + (size_t)bh * S_ * DK_;
    const float* Kp = g_K + (size_t)bh * S_ * DK_;
    const float* Vp = g_V + (size_t)bh * S_ * DK_;
    float*       Op = g_O + (size_t)bh * S_ * DK_;

    const int tid = threadIdx.x;
    const int wid = tid >> 5;
    const int lane = tid & 31;
    const int g = lane >> 2, t = lane & 3;
    const int wrow = wid * 16;          // warp's row base within the 128-tile
    const int q0 = qb * 128;

    // ---- load Q (scaled by 1/8), 32 floats per thread ----
    {
        const int r = tid >> 1;
        const int c0 = (tid & 1) * 32;
#pragma unroll
        for (int i = 0; i < 8; i++) {
            float4 q = *(const float4*)&Qp[(size_t)(q0 + r) * DK_ + c0 + 4 * i];
            Qs[r][c0 + 4 * i + 0] = q.x * 0.125f;
            Qs[r][c0 + 4 * i + 1] = q.y * 0.125f;
            Qs[r][c0 + 4 * i + 2] = q.z * 0.125f;
            Qs[r][c0 + 4 * i + 3] = q.w * 0.125f;
        }
    }

    float cO[8][4];
#pragma unroll
    for (int nf = 0; nf < 8; nf++)
#pragma unroll
        for (int q = 0; q < 4; q++) cO[nf][q] = 0.0f;
    float m0v = -1e30f, m1v = -1e30f, l0 = 0.0f, l1 = 0.0f;

    const int ntiles = 2 * qb + 2;

    // prefetch mappings
    const int krow = tid >> 4;            // 0..15 (+16p)
    const int kcol = (tid & 15) * 4;      // 0..60
    const int vc   = tid & 63;            // kv column
    const int vq   = tid >> 6;            // 0..3 -> d-base vq*16

    float4 kreg[4], vreg[4];
#pragma unroll
    for (int p = 0; p < 4; p++) {
        kreg[p] = *(const float4*)&Kp[(size_t)(krow + 16 * p) * DK_ + kcol];
        vreg[p] = *(const float4*)&Vp[(size_t)vc * DK_ + vq * 16 + 4 * p];
    }

    for (int kt = 0; kt < ntiles; kt++) {
        const int kv0 = kt * 64;
        __syncthreads();   // previous compute done reading K/V smem

        // ---- cooperative split & store (K direct, V transposed) ----
#pragma unroll
        for (int p = 0; p < 4; p++) {
            float4 k4 = kreg[p];
            uint32_t hx = cvt_tf32(k4.x), hy = cvt_tf32(k4.y),
                     hz = cvt_tf32(k4.z), hw = cvt_tf32(k4.w);
            *(float4*)&Khi[krow + 16 * p][kcol] =
                make_float4(__uint_as_float(hx), __uint_as_float(hy),
                            __uint_as_float(hz), __uint_as_float(hw));
            *(float4*)&Klo[krow + 16 * p][kcol] =
                make_float4(k4.x - __uint_as_float(hx), k4.y - __uint_as_float(hy),
                            k4.z - __uint_as_float(hz), k4.w - __uint_as_float(hw));
            float4 v4 = vreg[p];
            uint32_t ax = cvt_tf32(v4.x), ay = cvt_tf32(v4.y),
                     az = cvt_tf32(v4.z), aw = cvt_tf32(v4.w);
            const int d0 = vq * 16 + 4 * p;
            Vhi[d0 + 0][vc] = __uint_as_float(ax);
            Vhi[d0 + 1][vc] = __uint_as_float(ay);
            Vhi[d0 + 2][vc] = __uint_as_float(az);
            Vhi[d0 + 3][vc] = __uint_as_float(aw);
            Vlo[d0 + 0][vc] = v4.x - __uint_as_float(ax);
            Vlo[d0 + 1][vc] = v4.y - __uint_as_float(ay);
            Vlo[d0 + 2][vc] = v4.z - __uint_as_float(az);
            Vlo[d0 + 3][vc] = v4.w - __uint_as_float(aw);
        }
        __syncthreads();   // tiles (and, at kt=0, Qs) ready

        // ---- prefetch next tile into registers (overlaps compute) ----
        if (kt + 1 < ntiles) {
            const int nk = kv0 + 64;
#pragma unroll
            for (int p = 0; p < 4; p++) {
                kreg[p] = *(const float4*)&Kp[(size_t)(nk + krow + 16 * p) * DK_ + kcol];
                vreg[p] = *(const float4*)&Vp[(size_t)(nk + vc) * DK_ + vq * 16 + 4 * p];
            }
        }

        // warps beyond their causal diagonal skip compute (barriers already passed)
        if (kv0 > q0 + wrow + 15) continue;

        // ---- S = Q K^T (tf32 x3) ----
        float cS[8][4];
#pragma unroll
        for (int nf = 0; nf < 8; nf++)
#pragma unroll
            for (int q = 0; q < 4; q++) cS[nf][q] = 0.0f;

#pragma unroll
        for (int ks = 0; ks < 8; ks++) {
            const int kc = ks * 8;
            uint32_t ah[4], al[4];
            split2(Qs[wrow + g][kc + t],         ah[0], al[0]);
            split2(Qs[wrow + g + 8][kc + t],     ah[1], al[1]);
            split2(Qs[wrow + g][kc + t + 4],     ah[2], al[2]);
            split2(Qs[wrow + g + 8][kc + t + 4], ah[3], al[3]);
#pragma unroll
            for (int nf = 0; nf < 8; nf++) {
                const uint32_t bh0 = __float_as_uint(Khi[nf * 8 + g][kc + t]);
                const uint32_t bh1 = __float_as_uint(Khi[nf * 8 + g][kc + t + 4]);
                const uint32_t bl0 = __float_as_uint(Klo[nf * 8 + g][kc + t]);
                const uint32_t bl1 = __float_as_uint(Klo[nf * 8 + g][kc + t + 4]);
                mma8(cS[nf], ah[0], ah[1], ah[2], ah[3], bh0, bh1);
                mma8(cS[nf], ah[0], ah[1], ah[2], ah[3], bl0, bl1);
                mma8(cS[nf], al[0], al[1], al[2], al[3], bh0, bh1);
            }
        }

        // ---- causal mask (only tiles crossing this warp's diagonal) ----
        if (kv0 + 63 > q0 + wrow) {
            const int r0g = q0 + wrow + g;
            const int r1g = r0g + 8;
#pragma unroll
            for (int nf = 0; nf < 8; nf++) {
                const int col = kv0 + nf * 8 + 2 * t;
                if (col     > r0g) cS[nf][0] = -1e30f;
                if (col + 1 > r0g) cS[nf][1] = -1e30f;
                if (col     > r1g) cS[nf][2] = -1e30f;
                if (col + 1 > r1g) cS[nf][3] = -1e30f;
            }
        }

        // ---- online softmax (rows wrow+g, wrow+g+8; quad reduction) ----
        float mx0 = -1e30f, mx1 = -1e30f;
#pragma unroll
        for (int nf = 0; nf < 8; nf++) {
            mx0 = fmaxf(mx0, fmaxf(cS[nf][0], cS[nf][1]));
            mx1 = fmaxf(mx1, fmaxf(cS[nf][2], cS[nf][3]));
        }
        mx0 = fmaxf(mx0, __shfl_xor_sync(0xffffffffu, mx0, 1));
        mx0 = fmaxf(mx0, __shfl_xor_sync(0xffffffffu, mx0, 2));
        mx1 = fmaxf(mx1, __shfl_xor_sync(0xffffffffu, mx1, 1));
        mx1 = fmaxf(mx1, __shfl_xor_sync(0xffffffffu, mx1, 2));
        const float mn0 = fmaxf(m0v, mx0), mn1 = fmaxf(m1v, mx1);
        const float corr0 = __expf(m0v - mn0), corr1 = __expf(m1v - mn1);
        float rs0 = 0.0f, rs1 = 0.0f;
#pragma unroll
        for (int nf = 0; nf < 8; nf++) {
            const float p0 = __expf(cS[nf][0] - mn0);
            const float p1 = __expf(cS[nf][1] - mn0);
            const float p2 = __expf(cS[nf][2] - mn1);
            const float p3 = __expf(cS[nf][3] - mn1);
            rs0 += p0 + p1; rs1 += p2 + p3;
            *(float2*)&Ps[wrow + g][nf * 8 + 2 * t]     = make_float2(p0, p1);
            *(float2*)&Ps[wrow + g + 8][nf * 8 + 2 * t] = make_float2(p2, p3);
        }
        rs0 += __shfl_xor_sync(0xffffffffu, rs0, 1);
        rs0 += __shfl_xor_sync(0xffffffffu, rs0, 2);
        rs1 += __shfl_xor_sync(0xffffffffu, rs1, 1);
        rs1 += __shfl_xor_sync(0xffffffffu, rs1, 2);
        l0 = l0 * corr0 + rs0; l1 = l1 * corr1 + rs1;
        m0v = mn0; m1v = mn1;
#pragma unroll
        for (int nf = 0; nf < 8; nf++) {
            cO[nf][0] *= corr0; cO[nf][1] *= corr0;
            cO[nf][2] *= corr1; cO[nf][3] *= corr1;
        }
        __syncwarp();   // P rows visible within the owning warp

        // ---- O += P V (tf32 x3) ----
#pragma unroll
        for (int ks = 0; ks < 8; ks++) {
            const int kc = ks * 8;
            uint32_t ah[4], al[4];
            split2(Ps[wrow + g][kc + t],         ah[0], al[0]);
            split2(Ps[wrow + g + 8][kc + t],     ah[1], al[1]);
            split2(Ps[wrow + g][kc + t + 4],     ah[2], al[2]);
            split2(Ps[wrow + g + 8][kc + t + 4], ah[3], al[3]);
#pragma unroll
            for (int nf = 0; nf < 8; nf++) {
                const uint32_t bh0 = __float_as_uint(Vhi[nf * 8 + g][kc + t]);
                const uint32_t bh1 = __float_as_uint(Vhi[nf * 8 + g][kc + t + 4]);
                const uint32_t bl0 = __float_as_uint(Vlo[nf * 8 + g][kc + t]);
                const uint32_t bl1 = __float_as_uint(Vlo[nf * 8 + g][kc + t + 4]);
                mma8(cO[nf], ah[0], ah[1], ah[2], ah[3], bh0, bh1);
                mma8(cO[nf], ah[0], ah[1], ah[2], ah[3], bl0, bl1);
                mma8(cO[nf], al[0], al[1], al[2], al[3], bh0, bh1);
            }
        }
    }

    // ---- normalize + store O ----
    const float inv0 = 1.0f / l0, inv1 = 1.0f / l1;
#pragma unroll
    for (int nf = 0; nf < 8; nf++) {
        const int col = nf * 8 + 2 * t;
        *(float2*)&Op[(size_t)(q0 + wrow + g) * DK_ + col] =
            make_float2(cO[nf][0] * inv0, cO[nf][1] * inv0);
        *(float2*)&Op[(size_t)(q0 + wrow + g + 8) * DK_ + col] =
            make_float2(cO[nf][2] * inv1, cO[nf][3] * inv1);
    }
}

// ---------------------------------------------------------------------------
extern "C" void kernel_launch(void* const* d_in, const int* in_sizes, int n_in,
                              void* d_out, int out_size)
{
    const float* x  = (const float*)d_in[0];
    const float* Wq = (const float*)d_in[2];
    const float* bq = (const float*)d_in[3];
    const float* Wk = (const float*)d_in[4];
    const float* bk = (const float*)d_in[5];
    const float* Wv = (const float*)d_in[6];
    const float* bv = (const float*)d_in[7];
    const float* Wo = (const float*)d_in[8];
    const float* bo = (const float*)d_in[9];
    float* out = (float*)d_out;

    cudaFuncSetAttribute(qkv_mma, cudaFuncAttributeMaxDynamicSharedMemorySize, GEMM_SMEM);
    cudaFuncSetAttribute(out_mma, cudaFuncAttributeMaxDynamicSharedMemorySize, GEMM_SMEM);
    cudaFuncSetAttribute(attn_mma2, cudaFuncAttributeMaxDynamicSharedMemorySize, ATTN_SMEM);

    transpose_qkv<<<dim3(2, 32, 48), dim3(32, 8)>>>(Wq, Wk, Wv);
    transpose_wo<<<dim3(32, 32), dim3(32, 8)>>>(Wo);

    qkv_mma<<<dim3(M_ / 128, D_ / 128, 3), 256, GEMM_SMEM>>>(x, bq, bk, bv);

    attn_mma2<<<dim3(S_ / 128, B_ * H_), 256, ATTN_SMEM>>>();

    out_mma<<<dim3(M_ / 128, D_ / 128), 256, GEMM_SMEM>>>(bo, out);
}